// round 2
// baseline (speedup 1.0000x reference)
#include <cuda_runtime.h>
#include <math.h>

#define NANCH   8400
#define MAXB    32
#define NCLS    80
#define MAXDET  100
#define NBKT    1024
#define CHUNK   1024

// ---------------- device scratch (no allocations allowed) ----------------
__device__ float  g_scores[MAXB * NANCH];
__device__ float4 g_boxes [MAXB * NANCH];
__device__ int    g_labels[MAXB * NANCH];

__device__ __forceinline__ float sigmoidf_(float x) {
    return 1.0f / (1.0f + expf(-x));
}

// ---------------- decode: 4 anchors per thread, float4 loads ----------------
__global__ void __launch_bounds__(256) k_decode(
    const float* __restrict__ cls0, const float* __restrict__ reg0, const float* __restrict__ obj0,
    const float* __restrict__ cls1, const float* __restrict__ reg1, const float* __restrict__ obj1,
    const float* __restrict__ cls2, const float* __restrict__ reg2, const float* __restrict__ obj2)
{
    const int b = blockIdx.y;
    const int a = (blockIdx.x * blockDim.x + threadIdx.x) * 4;   // first of 4 anchors
    if (a >= NANCH) return;

    const float *cls, *reg, *obj;
    int a0, w, hw; float s;
    if (a < 6400)      { cls = cls0; reg = reg0; obj = obj0; a0 = a;        w = 80; hw = 6400; s = 8.0f;  }
    else if (a < 8000) { cls = cls1; reg = reg1; obj = obj1; a0 = a - 6400; w = 40; hw = 1600; s = 16.0f; }
    else               { cls = cls2; reg = reg2; obj = obj2; a0 = a - 8000; w = 20; hw = 400;  s = 32.0f; }

    const int hw4 = hw >> 2;
    const int q   = a0 >> 2;

    // ---- argmax over 80 classes, 4 anchors wide ----
    const float4* c4 = (const float4*)(cls + (size_t)b * NCLS * hw) + q;
    float4 v = c4[0];
    float m0 = v.x, m1 = v.y, m2 = v.z, m3 = v.w;
    int   l0 = 0,   l1 = 0,   l2 = 0,   l3 = 0;
    #pragma unroll 4
    for (int c = 1; c < NCLS; ++c) {
        v = c4[(size_t)c * hw4];
        if (v.x > m0) { m0 = v.x; l0 = c; }
        if (v.y > m1) { m1 = v.y; l1 = c; }
        if (v.z > m2) { m2 = v.z; l2 = c; }
        if (v.w > m3) { m3 = v.w; l3 = c; }
    }

    float4 ov = *((const float4*)(obj + (size_t)b * hw) + q);

    const float* rb = reg + (size_t)b * 4 * hw;
    float4 r0 = *((const float4*)(rb)          + q);
    float4 r1 = *((const float4*)(rb +     hw) + q);
    float4 r2 = *((const float4*)(rb + 2 * hw) + q);
    float4 r3 = *((const float4*)(rb + 3 * hw) + q);

    float mm[4] = { m0, m1, m2, m3 };
    int   ll[4] = { l0, l1, l2, l3 };
    float oo[4] = { ov.x, ov.y, ov.z, ov.w };
    float rx[4] = { r0.x, r0.y, r0.z, r0.w };
    float ry[4] = { r1.x, r1.y, r1.z, r1.w };
    float rw[4] = { r2.x, r2.y, r2.z, r2.w };
    float rh[4] = { r3.x, r3.y, r3.z, r3.w };

    const size_t base = (size_t)b * NANCH + a;
    float sc[4];
    #pragma unroll
    for (int i = 0; i < 4; ++i) {
        sc[i] = __fmul_rn(sigmoidf_(mm[i]), sigmoidf_(oo[i]));
        int ai = a0 + i;
        float px = (float)(ai % w) * s;   // exact (small ints * pow2)
        float py = (float)(ai / w) * s;
        float cx = __fadd_rn(__fmul_rn(rx[i], s), px);
        float cy = __fadd_rn(__fmul_rn(ry[i], s), py);
        float bw = __fmul_rn(expf(rw[i]), s);
        float bh = __fmul_rn(expf(rh[i]), s);
        float hx = __fmul_rn(bw, 0.5f);
        float hy = __fmul_rn(bh, 0.5f);
        g_boxes[base + i] = make_float4(__fsub_rn(cx, hx), __fsub_rn(cy, hy),
                                        __fadd_rn(cx, hx), __fadd_rn(cy, hy));
    }
    *((float4*)(g_scores + base)) = make_float4(sc[0], sc[1], sc[2], sc[3]);
    *((int4*)(g_labels + base))   = make_int4(ll[0], ll[1], ll[2], ll[3]);
}

// 64-bit shfl_xor helper
__device__ __forceinline__ unsigned long long shflx64(unsigned long long v, int j) {
    return __shfl_xor_sync(0xFFFFFFFFu, v, j);
}

// ---------------- NMS: box-max + histogram -> chunk -> hybrid bitonic -> greedy ----------------
__global__ void __launch_bounds__(1024) k_nms(float* __restrict__ out, int B)
{
    __shared__ int                s_hist[NBKT];
    __shared__ unsigned long long s_chunk[CHUNK];
    __shared__ float4             s_topbox[CHUNK];
    __shared__ float4             s_keptb[MAXDET];
    __shared__ int                s_kepti[MAXDET];
    __shared__ float              s_red[32];
    __shared__ float              s_off;
    __shared__ int                s_cnt, s_kc, s_lo, s_hi, s_ptr;

    const int b   = blockIdx.x;
    const int tid = threadIdx.x;
    const size_t base = (size_t)b * NANCH;

    if (tid == 0) { s_ptr = NBKT - 1; s_kc = 0; }
    s_hist[tid] = 0;
    __syncthreads();

    // ---- pass 1: max|box coord| (all anchors) + score histogram ----
    float mloc = 0.0f;
    for (int i = tid; i < NANCH; i += 1024) {
        float4 bx = g_boxes[base + i];
        mloc = fmaxf(mloc, fmaxf(fmaxf(fabsf(bx.x), fabsf(bx.y)),
                                 fmaxf(fabsf(bx.z), fabsf(bx.w))));
        float scv = g_scores[base + i];
        if (scv >= 0.01f) {
            int bkt = (int)(scv * 1024.0f);
            if (bkt > NBKT - 1) bkt = NBKT - 1;
            atomicAdd(&s_hist[bkt], 1);
        }
    }
    #pragma unroll
    for (int o = 16; o > 0; o >>= 1)
        mloc = fmaxf(mloc, __shfl_xor_sync(0xFFFFFFFFu, mloc, o));
    if ((tid & 31) == 0) s_red[tid >> 5] = mloc;
    __syncthreads();
    if (tid < 32) {
        float v = s_red[tid];
        #pragma unroll
        for (int o = 16; o > 0; o >>= 1)
            v = fmaxf(v, __shfl_xor_sync(0xFFFFFFFFu, v, o));
        if (tid == 0) s_off = __fadd_rn(v, 1.0f);
    }
    __syncthreads();
    const float off = s_off;

    for (;;) {
        __syncthreads();
        if (s_kc >= MAXDET || s_ptr < 0) break;

        if (tid == 0) {
            int acc = 0;
            int hi = s_ptr, p = hi;
            while (p >= 0) {
                int h = s_hist[p];
                if (acc > 0 && acc + h > CHUNK) break;
                acc += h; --p;
                if (acc >= 384) break;
            }
            s_lo = p + 1; s_hi = hi; s_ptr = p; s_cnt = 0;
        }
        __syncthreads();
        int lo = s_lo, hi = s_hi;

        // compact bucket range into chunk (key: score desc, idx asc)
        for (int i = tid; i < NANCH; i += 1024) {
            float scv = g_scores[base + i];
            if (scv >= 0.01f) {
                int bkt = (int)(scv * 1024.0f);
                if (bkt > NBKT - 1) bkt = NBKT - 1;
                if (bkt >= lo && bkt <= hi) {
                    int p = atomicAdd(&s_cnt, 1);
                    if (p < CHUNK) {
                        unsigned u = __float_as_uint(scv);
                        u = ~(u ^ 0x80000000u);
                        s_chunk[p] = ((unsigned long long)u << 32) | (unsigned)i;
                    }
                }
            }
        }
        __syncthreads();
        int cN = s_cnt; if (cN > CHUNK) cN = CHUNK;
        if (tid >= cN) s_chunk[tid] = 0xFFFFFFFFFFFFFFFFull;
        __syncthreads();

        // ---- hybrid bitonic sort: k=2..32 fused in registers ----
        {
            unsigned long long v = s_chunk[tid];
            #pragma unroll
            for (int k = 2; k <= 32; k <<= 1) {
                bool up = ((tid & k) == 0);
                #pragma unroll
                for (int j = k >> 1; j > 0; j >>= 1) {
                    unsigned long long p = shflx64(v, j);
                    bool keepSmall = (((tid & j) == 0) == up);
                    bool takeP = keepSmall ? (p < v) : (p > v);
                    if (takeP) v = p;
                }
            }
            s_chunk[tid] = v;
            __syncthreads();
        }
        // k=64..1024: smem stages for j>=32, register tail for j<=16
        for (int k = 64; k <= CHUNK; k <<= 1) {
            for (int j = k >> 1; j >= 32; j >>= 1) {
                int i = tid, l = i ^ j;
                if (l > i) {
                    unsigned long long A = s_chunk[i], Bv = s_chunk[l];
                    bool up = ((i & k) == 0);
                    if ((A > Bv) == up) { s_chunk[i] = Bv; s_chunk[l] = A; }
                }
                __syncthreads();
            }
            {
                unsigned long long v = s_chunk[tid];
                bool up = ((tid & k) == 0);
                #pragma unroll
                for (int j = 16; j > 0; j >>= 1) {
                    unsigned long long p = shflx64(v, j);
                    bool keepSmall = (((tid & j) == 0) == up);
                    bool takeP = keepSmall ? (p < v) : (p > v);
                    if (takeP) v = p;
                }
                s_chunk[tid] = v;
                __syncthreads();
            }
        }

        // gather class-offset boxes
        if (tid < cN) {
            int idx = (int)(s_chunk[tid] & 0xFFFFFFFFull);
            float4 bx = g_boxes[base + idx];
            float t = __fmul_rn((float)g_labels[base + idx], off);
            bx.x = __fadd_rn(bx.x, t);
            bx.y = __fadd_rn(bx.y, t);
            bx.z = __fadd_rn(bx.z, t);
            bx.w = __fadd_rn(bx.w, t);
            s_topbox[tid] = bx;
        }
        __syncthreads();

        // single-warp greedy scan
        if (tid < 32) {
            int lane = tid;
            int kc = s_kc;
            for (int c = 0; c < cN && kc < MAXDET; ++c) {
                float4 cbx = s_topbox[c];
                float ca = __fmul_rn(__fsub_rn(cbx.z, cbx.x), __fsub_rn(cbx.w, cbx.y));
                bool sup = false;
                for (int j = lane; j < kc; j += 32) {
                    float4 kb = s_keptb[j];
                    float tlx = fmaxf(kb.x, cbx.x), tly = fmaxf(kb.y, cbx.y);
                    float brx = fminf(kb.z, cbx.z), bry = fminf(kb.w, cbx.w);
                    float ww = fmaxf(__fsub_rn(brx, tlx), 0.0f);
                    float hh = fmaxf(__fsub_rn(bry, tly), 0.0f);
                    float inter = __fmul_rn(ww, hh);
                    float a1 = __fmul_rn(__fsub_rn(kb.z, kb.x), __fsub_rn(kb.w, kb.y));
                    float den = __fadd_rn(__fsub_rn(__fadd_rn(a1, ca), inter), 1e-6f);
                    if (__fdiv_rn(inter, den) > 0.65f) { sup = true; break; }
                }
                if (!__any_sync(0xFFFFFFFFu, sup)) {
                    if (lane == 0) {
                        s_keptb[kc] = cbx;
                        s_kepti[kc] = (int)(s_chunk[c] & 0xFFFFFFFFull);
                    }
                    ++kc;
                    __syncwarp();
                }
            }
            if (lane == 0) s_kc = kc;
        }
    }
    __syncthreads();

    // ---- write outputs: boxes | scores | labels | valid ----
    int kc = s_kc;
    float* ob  = out;
    float* osc = out + (size_t)B * MAXDET * 4;
    float* olb = osc + (size_t)B * MAXDET;
    float* ovl = olb + (size_t)B * MAXDET;

    if (tid < MAXDET) {
        int r = tid;
        float4 bx = make_float4(0.f, 0.f, 0.f, 0.f);
        float scv = 0.f, lb = -1.f, vl = 0.f;
        if (r < kc) {
            int idx = s_kepti[r];
            bx = g_boxes[base + idx];
            scv = g_scores[base + idx];
            lb = (float)g_labels[base + idx];
            vl = 1.0f;
        }
        float* obp = ob + ((size_t)b * MAXDET + r) * 4;
        obp[0] = bx.x; obp[1] = bx.y; obp[2] = bx.z; obp[3] = bx.w;
        osc[(size_t)b * MAXDET + r] = scv;
        olb[(size_t)b * MAXDET + r] = lb;
        ovl[(size_t)b * MAXDET + r] = vl;
    }
}

// ---------------- launch ----------------
extern "C" void kernel_launch(void* const* d_in, const int* in_sizes, int n_in,
                              void* d_out, int out_size)
{
    int B = in_sizes[0] / 512000;
    if (B < 1) B = 1;
    if (B > MAXB) B = MAXB;

    const float *cls[3], *reg[3], *obj[3];
    bool grouped = (n_in >= 9) && (in_sizes[1] == B * 128000);
    if (grouped) {
        for (int i = 0; i < 3; ++i) {
            cls[i] = (const float*)d_in[i];
            reg[i] = (const float*)d_in[3 + i];
            obj[i] = (const float*)d_in[6 + i];
        }
    } else {
        for (int i = 0; i < 3; ++i) {
            cls[i] = (const float*)d_in[3 * i];
            reg[i] = (const float*)d_in[3 * i + 1];
            obj[i] = (const float*)d_in[3 * i + 2];
        }
    }

    dim3 g1((NANCH / 4 + 255) / 256, B);   // 2100 threads per image, x4 anchors each
    k_decode<<<g1, 256>>>(cls[0], reg[0], obj[0],
                          cls[1], reg[1], obj[1],
                          cls[2], reg[2], obj[2]);
    k_nms<<<B, 1024>>>((float*)d_out, B);
}

// round 3
// speedup vs baseline: 1.1396x; 1.1396x over previous
#include <cuda_runtime.h>
#include <math.h>

#define NANCH   8400
#define MAXB    32
#define NCLS    80
#define MAXDET  100
#define NBKT    1024
#define CCAP    256      // chunk capacity (= NMS sort width)

// ---------------- device scratch (static zero-init; self-cleaning across graph replays) ----------------
__device__ float  g_scores[MAXB * NANCH];
__device__ float4 g_boxes [MAXB * NANCH];
__device__ int    g_labels[MAXB * NANCH];
__device__ int    g_maxabs[MAXB];          // float bits (non-negative), atomicMax
__device__ int    g_hist  [MAXB][NBKT];    // per-image score histogram

__device__ __forceinline__ float sigmoidf_(float x) {
    return 1.0f / (1.0f + expf(-x));
}

// ---------------- decode: 4 anchors/thread + histogram + boxmax fused ----------------
__global__ void __launch_bounds__(256) k_decode(
    const float* __restrict__ cls0, const float* __restrict__ reg0, const float* __restrict__ obj0,
    const float* __restrict__ cls1, const float* __restrict__ reg1, const float* __restrict__ obj1,
    const float* __restrict__ cls2, const float* __restrict__ reg2, const float* __restrict__ obj2)
{
    const int b = blockIdx.y;
    const int a = (blockIdx.x * blockDim.x + threadIdx.x) * 4;
    const bool act = (a < NANCH);
    float m4 = 0.0f;

    if (act) {
        const float *cls, *reg, *obj;
        int a0, w, hw; float s;
        if (a < 6400)      { cls = cls0; reg = reg0; obj = obj0; a0 = a;        w = 80; hw = 6400; s = 8.0f;  }
        else if (a < 8000) { cls = cls1; reg = reg1; obj = obj1; a0 = a - 6400; w = 40; hw = 1600; s = 16.0f; }
        else               { cls = cls2; reg = reg2; obj = obj2; a0 = a - 8000; w = 20; hw = 400;  s = 32.0f; }

        const int hw4 = hw >> 2;
        const int q   = a0 >> 2;

        const float4* c4 = (const float4*)(cls + (size_t)b * NCLS * hw) + q;
        float4 v = c4[0];
        float m0 = v.x, m1 = v.y, m2 = v.z, m3 = v.w;
        int   l0 = 0,   l1 = 0,   l2 = 0,   l3 = 0;
        #pragma unroll 4
        for (int c = 1; c < NCLS; ++c) {
            v = c4[(size_t)c * hw4];
            if (v.x > m0) { m0 = v.x; l0 = c; }
            if (v.y > m1) { m1 = v.y; l1 = c; }
            if (v.z > m2) { m2 = v.z; l2 = c; }
            if (v.w > m3) { m3 = v.w; l3 = c; }
        }

        float4 ov = *((const float4*)(obj + (size_t)b * hw) + q);
        const float* rb = reg + (size_t)b * 4 * hw;
        float4 r0 = *((const float4*)(rb)          + q);
        float4 r1 = *((const float4*)(rb +     hw) + q);
        float4 r2 = *((const float4*)(rb + 2 * hw) + q);
        float4 r3 = *((const float4*)(rb + 3 * hw) + q);

        float mm[4] = { m0, m1, m2, m3 };
        int   ll[4] = { l0, l1, l2, l3 };
        float oo[4] = { ov.x, ov.y, ov.z, ov.w };
        float rx[4] = { r0.x, r0.y, r0.z, r0.w };
        float ry[4] = { r1.x, r1.y, r1.z, r1.w };
        float rw[4] = { r2.x, r2.y, r2.z, r2.w };
        float rh[4] = { r3.x, r3.y, r3.z, r3.w };

        const size_t base = (size_t)b * NANCH + a;
        float sc[4];
        #pragma unroll
        for (int i = 0; i < 4; ++i) {
            sc[i] = __fmul_rn(sigmoidf_(mm[i]), sigmoidf_(oo[i]));
            int ai = a0 + i;
            float px = (float)(ai % w) * s;
            float py = (float)(ai / w) * s;
            float cx = __fadd_rn(__fmul_rn(rx[i], s), px);
            float cy = __fadd_rn(__fmul_rn(ry[i], s), py);
            float bw = __fmul_rn(expf(rw[i]), s);
            float bh = __fmul_rn(expf(rh[i]), s);
            float hx = __fmul_rn(bw, 0.5f);
            float hy = __fmul_rn(bh, 0.5f);
            float x1 = __fsub_rn(cx, hx), y1 = __fsub_rn(cy, hy);
            float x2 = __fadd_rn(cx, hx), y2 = __fadd_rn(cy, hy);
            g_boxes[base + i] = make_float4(x1, y1, x2, y2);
            m4 = fmaxf(m4, fmaxf(fmaxf(fabsf(x1), fabsf(y1)), fmaxf(fabsf(x2), fabsf(y2))));
            if (sc[i] >= 0.01f) {
                int bkt = (int)(sc[i] * 1024.0f);
                if (bkt > NBKT - 1) bkt = NBKT - 1;
                atomicAdd(&g_hist[b][bkt], 1);
            }
        }
        *((float4*)(g_scores + base)) = make_float4(sc[0], sc[1], sc[2], sc[3]);
        *((int4*)(g_labels + base))   = make_int4(ll[0], ll[1], ll[2], ll[3]);
    }

    // warp-reduce boxmax, one atomic per warp
    #pragma unroll
    for (int o = 16; o > 0; o >>= 1)
        m4 = fmaxf(m4, __shfl_xor_sync(0xFFFFFFFFu, m4, o));
    if ((threadIdx.x & 31) == 0 && m4 > 0.0f)
        atomicMax(&g_maxabs[b], __float_as_int(m4));
}

__device__ __forceinline__ unsigned long long shflx64(unsigned long long v, int j) {
    return __shfl_xor_sync(0xFFFFFFFFu, v, j);
}

// exact reference IoU>thr test on (already offset) boxes
__device__ __forceinline__ bool iou_gt(float4 a, float4 bx) {
    float tlx = fmaxf(a.x, bx.x), tly = fmaxf(a.y, bx.y);
    float brx = fminf(a.z, bx.z), bry = fminf(a.w, bx.w);
    float ww = fmaxf(__fsub_rn(brx, tlx), 0.0f);
    float hh = fmaxf(__fsub_rn(bry, tly), 0.0f);
    float inter = __fmul_rn(ww, hh);
    float a1 = __fmul_rn(__fsub_rn(a.z, a.x), __fsub_rn(a.w, a.y));
    float a2 = __fmul_rn(__fsub_rn(bx.z, bx.x), __fsub_rn(bx.w, bx.y));
    float den = __fadd_rn(__fsub_rn(__fadd_rn(a1, a2), inter), 1e-6f);
    return __fdiv_rn(inter, den) > 0.65f;
}

// ---------------- NMS: 256 threads, chunk=256, suppression matrix, warp greedy ----------------
__global__ void __launch_bounds__(256) k_nms(float* __restrict__ out, int B)
{
    __shared__ int                s_hist[NBKT];
    __shared__ unsigned long long s_key[CCAP];
    __shared__ float4             s_box[CCAP];
    __shared__ int                s_lab[CCAP];
    __shared__ unsigned           s_row[CCAP][8];
    __shared__ int                s_predead[CCAP];
    __shared__ float4             s_keptb[MAXDET];
    __shared__ int                s_klab[MAXDET];
    __shared__ int                s_kepti[MAXDET];
    __shared__ float              s_off;
    __shared__ int                s_cnt, s_kc, s_lo, s_hi, s_ptr;

    const int b   = blockIdx.x;
    const int tid = threadIdx.x;
    const size_t base = (size_t)b * NANCH;

    // load histogram into smem; zero global copy for next replay
    #pragma unroll
    for (int k = tid; k < NBKT; k += 256) {
        s_hist[k] = g_hist[b][k];
        g_hist[b][k] = 0;
    }
    if (tid == 0) {
        s_off = __fadd_rn(__int_as_float(g_maxabs[b]), 1.0f);
        g_maxabs[b] = 0;
        s_ptr = NBKT - 1;
        s_kc = 0;
    }
    __syncthreads();
    const float off = s_off;

    for (;;) {
        __syncthreads();
        if (s_kc >= MAXDET || s_ptr < 0) break;

        if (tid == 0) {
            int acc = 0;
            int hi = s_ptr, p = hi;
            while (p >= 0) {
                int h = s_hist[p];
                if (acc > 0 && acc + h > CCAP) break;
                acc += h; --p;
                if (acc >= CCAP) break;
            }
            s_lo = p + 1; s_hi = hi; s_ptr = p; s_cnt = 0;
        }
        __syncthreads();
        const int lo = s_lo, hi = s_hi;

        // compact: one vectorized sweep over scores
        for (int i4 = tid; i4 < NANCH / 4; i4 += 256) {
            float4 s4 = *((const float4*)(g_scores + base) + i4);
            float sv[4] = { s4.x, s4.y, s4.z, s4.w };
            #pragma unroll
            for (int k = 0; k < 4; ++k) {
                float scv = sv[k];
                if (scv >= 0.01f) {
                    int bkt = (int)(scv * 1024.0f);
                    if (bkt > NBKT - 1) bkt = NBKT - 1;
                    if (bkt >= lo && bkt <= hi) {
                        int p = atomicAdd(&s_cnt, 1);
                        if (p < CCAP) {
                            unsigned u = __float_as_uint(scv);
                            u = ~(u ^ 0x80000000u);
                            s_key[p] = ((unsigned long long)u << 32) | (unsigned)(i4 * 4 + k);
                        }
                    }
                }
            }
        }
        __syncthreads();
        int cN = s_cnt; if (cN > CCAP) cN = CCAP;
        if (tid >= cN) s_key[tid] = 0xFFFFFFFFFFFFFFFFull;
        __syncthreads();

        // bitonic sort 256 keys ascending (= score desc, idx asc)
        {
            unsigned long long v = s_key[tid];
            #pragma unroll
            for (int k = 2; k <= 32; k <<= 1) {
                bool up = ((tid & k) == 0);
                #pragma unroll
                for (int j = k >> 1; j > 0; j >>= 1) {
                    unsigned long long p = shflx64(v, j);
                    bool keepSmall = (((tid & j) == 0) == up);
                    if (keepSmall ? (p < v) : (p > v)) v = p;
                }
            }
            s_key[tid] = v;
            __syncthreads();
        }
        #pragma unroll
        for (int k = 64; k <= CCAP; k <<= 1) {
            for (int j = k >> 1; j >= 32; j >>= 1) {
                int i = tid, l = i ^ j;
                if (l > i) {
                    unsigned long long A = s_key[i], Bv = s_key[l];
                    bool up = ((i & k) == 0);
                    if ((A > Bv) == up) { s_key[i] = Bv; s_key[l] = A; }
                }
                __syncthreads();
            }
            {
                unsigned long long v = s_key[tid];
                bool up = ((tid & k) == 0);
                #pragma unroll
                for (int j = 16; j > 0; j >>= 1) {
                    unsigned long long p = shflx64(v, j);
                    bool keepSmall = (((tid & j) == 0) == up);
                    if (keepSmall ? (p < v) : (p > v)) v = p;
                }
                s_key[tid] = v;
                __syncthreads();
            }
        }

        // gather shifted boxes + labels; predead vs previously-kept
        float4 mybox; int mylab = -1;
        if (tid < cN) {
            int idx = (int)(s_key[tid] & 0xFFFFFFFFull);
            mybox = g_boxes[base + idx];
            mylab = g_labels[base + idx];
            float t = __fmul_rn((float)mylab, off);
            mybox.x = __fadd_rn(mybox.x, t);
            mybox.y = __fadd_rn(mybox.y, t);
            mybox.z = __fadd_rn(mybox.z, t);
            mybox.w = __fadd_rn(mybox.w, t);
            s_box[tid] = mybox;
            s_lab[tid] = mylab;
            int dead = 0;
            int kc0 = s_kc;
            for (int j = 0; j < kc0; ++j)
                if (s_klab[j] == mylab && iou_gt(s_keptb[j], mybox)) { dead = 1; break; }
            s_predead[tid] = dead;
        }
        __syncthreads();

        // suppression rows: bit j set iff earlier candidate j suppresses me
        if (tid < cN) {
            unsigned r[8] = {0,0,0,0,0,0,0,0};
            for (int j = 0; j < tid; ++j) {
                if (s_lab[j] == mylab && iou_gt(s_box[j], mybox))
                    r[j >> 5] |= (1u << (j & 31));
            }
            #pragma unroll
            for (int wdi = 0; wdi < 8; ++wdi) s_row[tid][wdi] = r[wdi];
        }
        __syncthreads();

        // warp greedy over kept-bitmask
        if (tid < 32) {
            unsigned keptw = 0;            // lanes 0..7 own 32 candidates each
            int kc = s_kc;
            int lane = tid;
            for (int c = 0; c < cN && kc < MAXDET; ++c) {
                unsigned hit = (lane < 8) ? (s_row[c][lane] & keptw) : 0u;
                bool dead = __any_sync(0xFFFFFFFFu, hit != 0u) || (s_predead[c] != 0);
                if (!dead) {
                    if (lane == (c >> 5)) keptw |= (1u << (c & 31));
                    if (lane == 0) {
                        s_keptb[kc] = s_box[c];
                        s_klab[kc]  = s_lab[c];
                        s_kepti[kc] = (int)(s_key[c] & 0xFFFFFFFFull);
                    }
                    ++kc;
                }
            }
            if (lane == 0) s_kc = kc;
        }
    }
    __syncthreads();

    // ---- outputs: boxes | scores | labels | valid ----
    int kc = s_kc;
    float* ob  = out;
    float* osc = out + (size_t)B * MAXDET * 4;
    float* olb = osc + (size_t)B * MAXDET;
    float* ovl = olb + (size_t)B * MAXDET;

    if (tid < MAXDET) {
        int r = tid;
        float4 bx = make_float4(0.f, 0.f, 0.f, 0.f);
        float scv = 0.f, lb = -1.f, vl = 0.f;
        if (r < kc) {
            int idx = s_kepti[r];
            bx = g_boxes[base + idx];
            scv = g_scores[base + idx];
            lb = (float)g_labels[base + idx];
            vl = 1.0f;
        }
        float* obp = ob + ((size_t)b * MAXDET + r) * 4;
        obp[0] = bx.x; obp[1] = bx.y; obp[2] = bx.z; obp[3] = bx.w;
        osc[(size_t)b * MAXDET + r] = scv;
        olb[(size_t)b * MAXDET + r] = lb;
        ovl[(size_t)b * MAXDET + r] = vl;
    }
}

// ---------------- launch ----------------
extern "C" void kernel_launch(void* const* d_in, const int* in_sizes, int n_in,
                              void* d_out, int out_size)
{
    int B = in_sizes[0] / 512000;
    if (B < 1) B = 1;
    if (B > MAXB) B = MAXB;

    const float *cls[3], *reg[3], *obj[3];
    bool grouped = (n_in >= 9) && (in_sizes[1] == B * 128000);
    if (grouped) {
        for (int i = 0; i < 3; ++i) {
            cls[i] = (const float*)d_in[i];
            reg[i] = (const float*)d_in[3 + i];
            obj[i] = (const float*)d_in[6 + i];
        }
    } else {
        for (int i = 0; i < 3; ++i) {
            cls[i] = (const float*)d_in[3 * i];
            reg[i] = (const float*)d_in[3 * i + 1];
            obj[i] = (const float*)d_in[3 * i + 2];
        }
    }

    dim3 g1((NANCH / 4 + 255) / 256, B);
    k_decode<<<g1, 256>>>(cls[0], reg[0], obj[0],
                          cls[1], reg[1], obj[1],
                          cls[2], reg[2], obj[2]);
    k_nms<<<B, 256>>>((float*)d_out, B);
}